// round 2
// baseline (speedup 1.0000x reference)
#include <cuda_runtime.h>

#define NN 400
#define FF 240
#define CC 32
#define LL 1440
#define SIN_X2 480   // row index of swE in sw; swEt at 481

// ---- scratch (device globals; no allocation allowed) ----
__device__ float g_Xi[NN * CC];
__device__ float g_Xj[NN * CC];
__device__ float g_aggI[NN * CC];
__device__ float g_aggJ[NN * CC];
__device__ float g_e1[NN * NN];
__device__ float g_e1T[NN * NN];
__device__ float g_aT[NN * NN];
__device__ float g_eT[NN * NN];
__device__ float g_x1[NN * FF];
__device__ float g_x2[NN * FF];

// ============================================================
// K0: transpose a -> g_aT, e -> g_eT (32x32 tiles, 256 thr)
// grid (169, 2): y=0 -> a, y=1 -> e
// ============================================================
__global__ void __launch_bounds__(256) prep_kernel(
    const float* __restrict__ a, const float* __restrict__ e)
{
    __shared__ float t[32][33];
    const float* src = blockIdx.y ? e : a;
    float* dst = blockIdx.y ? g_eT : g_aT;
    int bx = blockIdx.x % 13, by = blockIdx.x / 13;
    int x0 = bx * 32, y0 = by * 32;
    int tx = threadIdx.x & 31, ty = threadIdx.x >> 5;
#pragma unroll
    for (int r = 0; r < 32; r += 8) {
        int y = y0 + ty + r, x = x0 + tx;
        if (y < NN && x < NN) t[ty + r][tx] = src[y * NN + x];
    }
    __syncthreads();
#pragma unroll
    for (int r = 0; r < 32; r += 8) {
        int y = x0 + ty + r, x = y0 + tx;
        if (y < NN && x < NN) dst[y * NN + x] = t[tx][ty + r];
    }
}

// ============================================================
// K1: Xi = x @ sw[0:F] + sb,  Xj = x @ sw[F:2F]
// 4 independent accumulators -> chain length 60 instead of 240
// ============================================================
__global__ void __launch_bounds__(256) xw_kernel(
    const float* __restrict__ xin, const float* __restrict__ sw,
    const float* __restrict__ sb, int useX1)
{
    const float* x = useX1 ? g_x1 : xin;
    __shared__ __align__(16) float sx[4][FF];
    int row0 = blockIdx.x * 4;
    for (int idx = threadIdx.x; idx < 4 * FF; idx += blockDim.x)
        sx[idx / FF][idx % FF] = x[row0 * FF + idx];
    __syncthreads();

    int w = threadIdx.x >> 5, c = threadIdx.x & 31;
    int r = w & 3;
    bool isJ = (w >= 4);
    const float* wb = sw + (isJ ? FF * CC : 0) + c;
    float a0 = isJ ? 0.f : sb[c];
    float a1 = 0.f, a2 = 0.f, a3 = 0.f;
    const float4* sxr = (const float4*)sx[r];
#pragma unroll 6
    for (int f4 = 0; f4 < FF / 4; f4++) {
        float4 xv = sxr[f4];
        int f = f4 * 4;
        a0 += xv.x * __ldg(wb + (f + 0) * CC);
        a1 += xv.y * __ldg(wb + (f + 1) * CC);
        a2 += xv.z * __ldg(wb + (f + 2) * CC);
        a3 += xv.w * __ldg(wb + (f + 3) * CC);
    }
    (isJ ? g_Xj : g_Xi)[(row0 + r) * CC + c] = (a0 + a1) + (a2 + a3);
}

// ============================================================
// K2: per-pair kernel. Grid = 800 blocks:
//   blocks [0,400)   : row mode  (fixed i, loop j) -> aggI, e1 row
//   blocks [400,800) : col mode  (fixed j, loop i) -> aggJ, e1T row
// All hot-loop loads are coalesced (uses pre-transposed a/e).
// Block reduction via shared memory (no shuffle storm).
// ============================================================
__global__ void __launch_bounds__(128) pair_kernel(
    const float* __restrict__ eParam, const float* __restrict__ a,
    const float* __restrict__ sw,
    const float* __restrict__ aiw, const float* __restrict__ aib,
    const float* __restrict__ ajw, const float* __restrict__ ajb,
    const float* __restrict__ ew,  const float* __restrict__ eb,
    int layer)
{
    const float* e  = (layer == 2) ? g_e1  : eParam;
    const float* eT = (layer == 2) ? g_e1T : g_eT;
    bool colMode = (blockIdx.x >= NN);
    int fixed = colMode ? (blockIdx.x - NN) : blockIdx.x;

    // pA: multiplies swE (eij), pB: multiplies swEt (eji), pAdj: adjacency
    const float* pA   = (colMode ? eT : e)  + fixed * NN;
    const float* pB   = (colMode ? e  : eT) + fixed * NN;
    const float* pAdj = (colMode ? g_aT : a) + fixed * NN;
    const float* pX   = colMode ? g_Xi : g_Xj;

    __shared__ __align__(16) float4 q[CC];  // (fixVec, swE, swEt, gateW)
    __shared__ float sEw[CC];
    __shared__ float sAcc[128][CC + 1];
    __shared__ float sPart[4][CC];

    int tid = threadIdx.x;
    if (tid < CC) {
        float fx = colMode ? g_Xj[fixed * CC + tid] : g_Xi[fixed * CC + tid];
        float gw = colMode ? ajw[tid] : aiw[tid];
        q[tid] = make_float4(fx, sw[SIN_X2 * CC + tid], sw[(SIN_X2 + 1) * CC + tid], gw);
        sEw[tid] = ew[tid];
    }
    __syncthreads();

    float gb  = colMode ? ajb[0] : aib[0];
    float ebv = eb[0];
    bool writeE = (layer == 1);
    float* eOut = (colMode ? g_e1T : g_e1) + fixed * NN;

    float acc[CC];
#pragma unroll
    for (int c = 0; c < CC; c++) acc[c] = 0.f;

    for (int v = tid; v < NN; v += 128) {
        float eij = __ldg(pA + v);
        float eji = __ldg(pB + v);
        float av  = __ldg(pAdj + v);
        const float4* vr = (const float4*)(pX + v * CC);

        float s = 0.f, se = 0.f;
        float tv[CC];
#pragma unroll
        for (int c4 = 0; c4 < CC / 4; c4++) {
            float4 vv = vr[c4];
            float vvals[4] = {vv.x, vv.y, vv.z, vv.w};
#pragma unroll
            for (int u = 0; u < 4; u++) {
                int c = c4 * 4 + u;
                float4 qq = q[c];
                float t = qq.x + vvals[u] + eij * qq.y + eji * qq.z;
                t = fmaxf(t, 0.f) * av;
                tv[c] = t;
                s  += t * qq.w;
                se += t * sEw[c];
            }
        }
        float gate = 1.f / (1.f + __expf(-(s + gb)));
#pragma unroll
        for (int c = 0; c < CC; c++) acc[c] += gate * tv[c];
        if (writeE) eOut[v] = se + ebv;
    }

    // block reduce via shared memory
#pragma unroll
    for (int c = 0; c < CC; c++) sAcc[tid][c] = acc[c];
    __syncthreads();
    {
        int w = tid >> 5, c = tid & 31;
        float p = 0.f;
#pragma unroll
        for (int k = 0; k < 32; k++) p += sAcc[w * 32 + k][c];
        sPart[w][c] = p;
    }
    __syncthreads();
    if (tid < CC) {
        float r = (sPart[0][tid] + sPart[1][tid]) + (sPart[2][tid] + sPart[3][tid]);
        (colMode ? g_aggJ : g_aggI)[fixed * CC + tid] = r;
    }
}

// ============================================================
// K3: node model  x_out = [x, aggI, aggJ] @ nw + nb  (K=304, M=240)
// 2-way K-split accumulators per row -> chain 152
// ============================================================
#define NK 304
__global__ void __launch_bounds__(256) node_kernel(
    const float* __restrict__ xin, const float* __restrict__ nw,
    const float* __restrict__ nb, int layer)
{
    const float* x = (layer == 1) ? xin : g_x1;
    float* xout = (layer == 1) ? g_x1 : g_x2;
    __shared__ __align__(16) float s[4][NK];
    int row0 = blockIdx.x * 4;
    for (int idx = threadIdx.x; idx < 4 * NK; idx += blockDim.x) {
        int r = idx / NK, k = idx % NK;
        float v;
        if (k < FF)            v = x[(row0 + r) * FF + k];
        else if (k < FF + CC)  v = g_aggI[(row0 + r) * CC + (k - FF)];
        else                   v = g_aggJ[(row0 + r) * CC + (k - FF - CC)];
        s[r][k] = v;
    }
    __syncthreads();

    int f = threadIdx.x;
    if (f < FF) {
        float b = nb[f];
        const float* wp = nw + f;
        float a0 = b, a1 = b, a2 = b, a3 = b;
        float b0 = 0.f, b1 = 0.f, b2 = 0.f, b3 = 0.f;
#pragma unroll 4
        for (int k8 = 0; k8 < NK / 8; k8++) {
            int k = k8 * 8;
            float w0 = __ldg(wp + (k + 0) * FF);
            float w1 = __ldg(wp + (k + 1) * FF);
            float w2 = __ldg(wp + (k + 2) * FF);
            float w3 = __ldg(wp + (k + 3) * FF);
            float w4 = __ldg(wp + (k + 4) * FF);
            float w5 = __ldg(wp + (k + 5) * FF);
            float w6 = __ldg(wp + (k + 6) * FF);
            float w7 = __ldg(wp + (k + 7) * FF);
            float4 x0 = *(const float4*)&s[0][k];
            float4 x0b = *(const float4*)&s[0][k + 4];
            float4 x1 = *(const float4*)&s[1][k];
            float4 x1b = *(const float4*)&s[1][k + 4];
            float4 x2 = *(const float4*)&s[2][k];
            float4 x2b = *(const float4*)&s[2][k + 4];
            float4 x3 = *(const float4*)&s[3][k];
            float4 x3b = *(const float4*)&s[3][k + 4];
            a0 += x0.x * w0 + x0.y * w1 + x0.z * w2 + x0.w * w3;
            b0 += x0b.x * w4 + x0b.y * w5 + x0b.z * w6 + x0b.w * w7;
            a1 += x1.x * w0 + x1.y * w1 + x1.z * w2 + x1.w * w3;
            b1 += x1b.x * w4 + x1b.y * w5 + x1b.z * w6 + x1b.w * w7;
            a2 += x2.x * w0 + x2.y * w1 + x2.z * w2 + x2.w * w3;
            b2 += x2b.x * w4 + x2b.y * w5 + x2b.z * w6 + x2b.w * w7;
            a3 += x3.x * w0 + x3.y * w1 + x3.z * w2 + x3.w * w3;
            b3 += x3b.x * w4 + x3b.y * w5 + x3b.z * w6 + x3b.w * w7;
        }
        xout[(row0 + 0) * FF + f] = a0 + b0;
        xout[(row0 + 1) * FF + f] = a1 + b1;
        xout[(row0 + 2) * FF + f] = a2 + b2;
        xout[(row0 + 3) * FF + f] = a3 + b3;
    }
}

// ============================================================
// K4: out = x2 @ dw + db   (400 x 1440, K=240)
// 16 rows x 256 cols per block; grid (6, 25)
// s[r][k] reads are warp-broadcast (conflict-free)
// ============================================================
#define ROWS_O 16
__global__ void __launch_bounds__(256) out_kernel(
    const float* __restrict__ dw, const float* __restrict__ db,
    float* __restrict__ out)
{
    __shared__ __align__(16) float s[ROWS_O][FF];
    int row0 = blockIdx.y * ROWS_O;
    int col = blockIdx.x * 256 + threadIdx.x;
    for (int idx = threadIdx.x; idx < ROWS_O * FF; idx += 256)
        s[idx / FF][idx % FF] = g_x2[row0 * FF + idx];
    __syncthreads();
    if (col >= LL) return;

    float b = db[col];
    const float* wp = dw + col;
    float acc[ROWS_O];
#pragma unroll
    for (int r = 0; r < ROWS_O; r++) acc[r] = b;

#pragma unroll 4
    for (int k4 = 0; k4 < FF / 4; k4++) {
        int k = k4 * 4;
        float w0 = __ldg(wp + (k + 0) * LL);
        float w1 = __ldg(wp + (k + 1) * LL);
        float w2 = __ldg(wp + (k + 2) * LL);
        float w3 = __ldg(wp + (k + 3) * LL);
#pragma unroll
        for (int r = 0; r < ROWS_O; r++) {
            float4 xv = *(const float4*)&s[r][k];
            acc[r] += xv.x * w0 + xv.y * w1 + xv.z * w2 + xv.w * w3;
        }
    }
#pragma unroll
    for (int r = 0; r < ROWS_O; r++)
        out[(row0 + r) * LL + col] = acc[r];
}

// ============================================================
extern "C" void kernel_launch(void* const* d_in, const int* in_sizes, int n_in,
                              void* d_out, int out_size)
{
    const float* x      = (const float*)d_in[0];
    const float* a      = (const float*)d_in[1];
    const float* e      = (const float*)d_in[2];
    const float* c1_sw  = (const float*)d_in[3];
    const float* c1_sb  = (const float*)d_in[4];
    const float* c1_aiw = (const float*)d_in[5];
    const float* c1_aib = (const float*)d_in[6];
    const float* c1_ajw = (const float*)d_in[7];
    const float* c1_ajb = (const float*)d_in[8];
    const float* c1_nw  = (const float*)d_in[9];
    const float* c1_nb  = (const float*)d_in[10];
    const float* c1_ew  = (const float*)d_in[11];
    const float* c1_eb  = (const float*)d_in[12];
    const float* c2_sw  = (const float*)d_in[13];
    const float* c2_sb  = (const float*)d_in[14];
    const float* c2_aiw = (const float*)d_in[15];
    const float* c2_aib = (const float*)d_in[16];
    const float* c2_ajw = (const float*)d_in[17];
    const float* c2_ajb = (const float*)d_in[18];
    const float* c2_nw  = (const float*)d_in[19];
    const float* c2_nb  = (const float*)d_in[20];
    const float* c2_ew  = (const float*)d_in[21];
    const float* c2_eb  = (const float*)d_in[22];
    const float* dw     = (const float*)d_in[23];
    const float* db     = (const float*)d_in[24];
    float* out = (float*)d_out;

    // ---- prep: transpose a, e ----
    prep_kernel<<<dim3(169, 2), 256>>>(a, e);

    // ---- layer 1 ----
    xw_kernel<<<NN / 4, 256>>>(x, c1_sw, c1_sb, 0);
    pair_kernel<<<2 * NN, 128>>>(e, a, c1_sw, c1_aiw, c1_aib, c1_ajw, c1_ajb,
                                 c1_ew, c1_eb, 1);
    node_kernel<<<NN / 4, 256>>>(x, c1_nw, c1_nb, 1);

    // ---- layer 2 (e input = g_e1/g_e1T; e_out not needed) ----
    xw_kernel<<<NN / 4, 256>>>(nullptr, c2_sw, c2_sb, 1);
    pair_kernel<<<2 * NN, 128>>>(nullptr, a, c2_sw, c2_aiw, c2_aib, c2_ajw, c2_ajb,
                                 c2_ew, c2_eb, 2);
    node_kernel<<<NN / 4, 256>>>(nullptr, c2_nw, c2_nb, 2);

    // ---- readout ----
    out_kernel<<<dim3(6, NN / ROWS_O), 256>>>(dw, db, out);
}

// round 3
// speedup vs baseline: 1.3222x; 1.3222x over previous
#include <cuda_runtime.h>

#define NN 400
#define FF 240
#define CC 32
#define LL 1440
#define NK 304
#define SIN_X2 480   // row index of swE in sw; swEt at 481

// ---- scratch (device globals; no allocation allowed) ----
__device__ float g_Xi[NN * CC];
__device__ float g_Xj[NN * CC];
__device__ float g_aggI[NN * CC];
__device__ float g_aggJ[NN * CC];
__device__ float g_e1[NN * NN];
__device__ float g_e1T[NN * NN];
__device__ float g_aT[NN * NN];
__device__ float g_eT[NN * NN];
__device__ float g_x1[NN * FF];
__device__ float g_x2[NN * FF];

// ============================================================
// K0: transpose a -> g_aT, e -> g_eT (32x32 tiles, 256 thr)
// ============================================================
__global__ void __launch_bounds__(256) prep_kernel(
    const float* __restrict__ a, const float* __restrict__ e)
{
    __shared__ float t[32][33];
    const float* src = blockIdx.y ? e : a;
    float* dst = blockIdx.y ? g_eT : g_aT;
    int bx = blockIdx.x % 13, by = blockIdx.x / 13;
    int x0 = bx * 32, y0 = by * 32;
    int tx = threadIdx.x & 31, ty = threadIdx.x >> 5;
#pragma unroll
    for (int r = 0; r < 32; r += 8) {
        int y = y0 + ty + r, x = x0 + tx;
        if (y < NN && x < NN) t[ty + r][tx] = src[y * NN + x];
    }
    __syncthreads();
#pragma unroll
    for (int r = 0; r < 32; r += 8) {
        int y = x0 + ty + r, x = y0 + tx;
        if (y < NN && x < NN) dst[y * NN + x] = t[tx][ty + r];
    }
}

// ============================================================
// K1: Xi = x @ sw[0:F] + sb,  Xj = x @ sw[F:2F]
// 1024 threads: tid>>8 = K-quarter (60 each); within 256:
// warps 0-3 -> Xi rows 0-3, warps 4-7 -> Xj rows 0-3.
// smem reduction over the 4 quarters.
// ============================================================
__global__ void __launch_bounds__(1024) xw_kernel(
    const float* __restrict__ xin, const float* __restrict__ sw,
    const float* __restrict__ sb, int useX1)
{
    const float* x = useX1 ? g_x1 : xin;
    __shared__ __align__(16) float sx[4][FF];
    __shared__ float part[4][8][CC];
    int row0 = blockIdx.x * 4;
    int tid = threadIdx.x;
    for (int idx = tid; idx < 4 * FF; idx += 1024)
        sx[idx / FF][idx % FF] = x[row0 * FF + idx];
    __syncthreads();

    int kq = tid >> 8;
    int t2 = tid & 255;
    int w = t2 >> 5, c = t2 & 31;
    int r = w & 3;
    bool isJ = (w >= 4);
    const float* wb = sw + (isJ ? FF * CC : 0) + c + kq * 60 * CC;
    float a0 = 0.f, a1 = 0.f, a2 = 0.f, a3 = 0.f;
    const float4* sxr = (const float4*)sx[r] + kq * 15;
#pragma unroll
    for (int f4 = 0; f4 < 15; f4++) {
        float4 xv = sxr[f4];
        int f = f4 * 4;
        a0 += xv.x * __ldg(wb + (f + 0) * CC);
        a1 += xv.y * __ldg(wb + (f + 1) * CC);
        a2 += xv.z * __ldg(wb + (f + 2) * CC);
        a3 += xv.w * __ldg(wb + (f + 3) * CC);
    }
    part[kq][w][c] = (a0 + a1) + (a2 + a3);
    __syncthreads();
    if (kq == 0) {
        float v = (part[0][w][c] + part[1][w][c]) + (part[2][w][c] + part[3][w][c]);
        if (!isJ) v += sb[c];
        (isJ ? g_Xj : g_Xi)[(row0 + r) * CC + c] = v;
    }
}

// ============================================================
// K2: per-pair kernel. Grid = 800 blocks (already ~21 warps/SM):
//   blocks [0,400)   : row mode  (fixed i, loop j) -> aggI, e1 row
//   blocks [400,800) : col mode  (fixed j, loop i) -> aggJ, e1T row
// ============================================================
__global__ void __launch_bounds__(128) pair_kernel(
    const float* __restrict__ eParam, const float* __restrict__ a,
    const float* __restrict__ sw,
    const float* __restrict__ aiw, const float* __restrict__ aib,
    const float* __restrict__ ajw, const float* __restrict__ ajb,
    const float* __restrict__ ew,  const float* __restrict__ eb,
    int layer)
{
    const float* e  = (layer == 2) ? g_e1  : eParam;
    const float* eT = (layer == 2) ? g_e1T : g_eT;
    bool colMode = (blockIdx.x >= NN);
    int fixed = colMode ? (blockIdx.x - NN) : blockIdx.x;

    const float* pA   = (colMode ? eT : e)  + fixed * NN;
    const float* pB   = (colMode ? e  : eT) + fixed * NN;
    const float* pAdj = (colMode ? g_aT : a) + fixed * NN;
    const float* pX   = colMode ? g_Xi : g_Xj;

    __shared__ __align__(16) float4 q[CC];  // (fixVec, swE, swEt, gateW)
    __shared__ float sEw[CC];
    __shared__ float sAcc[128][CC + 1];
    __shared__ float sPart[4][CC];

    int tid = threadIdx.x;
    if (tid < CC) {
        float fx = colMode ? g_Xj[fixed * CC + tid] : g_Xi[fixed * CC + tid];
        float gw = colMode ? ajw[tid] : aiw[tid];
        q[tid] = make_float4(fx, sw[SIN_X2 * CC + tid], sw[(SIN_X2 + 1) * CC + tid], gw);
        sEw[tid] = ew[tid];
    }
    __syncthreads();

    float gb  = colMode ? ajb[0] : aib[0];
    float ebv = eb[0];
    bool writeE = (layer == 1);
    float* eOut = (colMode ? g_e1T : g_e1) + fixed * NN;

    float acc[CC];
#pragma unroll
    for (int c = 0; c < CC; c++) acc[c] = 0.f;

    for (int v = tid; v < NN; v += 128) {
        float eij = __ldg(pA + v);
        float eji = __ldg(pB + v);
        float av  = __ldg(pAdj + v);
        const float4* vr = (const float4*)(pX + v * CC);

        float s = 0.f, se = 0.f;
        float tv[CC];
#pragma unroll
        for (int c4 = 0; c4 < CC / 4; c4++) {
            float4 vv = vr[c4];
            float vvals[4] = {vv.x, vv.y, vv.z, vv.w};
#pragma unroll
            for (int u = 0; u < 4; u++) {
                int c = c4 * 4 + u;
                float4 qq = q[c];
                float t = qq.x + vvals[u] + eij * qq.y + eji * qq.z;
                t = fmaxf(t, 0.f) * av;
                tv[c] = t;
                s  += t * qq.w;
                se += t * sEw[c];
            }
        }
        float gate = 1.f / (1.f + __expf(-(s + gb)));
#pragma unroll
        for (int c = 0; c < CC; c++) acc[c] += gate * tv[c];
        if (writeE) eOut[v] = se + ebv;
    }

#pragma unroll
    for (int c = 0; c < CC; c++) sAcc[tid][c] = acc[c];
    __syncthreads();
    {
        int w = tid >> 5, c = tid & 31;
        float p = 0.f;
#pragma unroll
        for (int k = 0; k < 32; k++) p += sAcc[w * 32 + k][c];
        sPart[w][c] = p;
    }
    __syncthreads();
    if (tid < CC) {
        float r = (sPart[0][tid] + sPart[1][tid]) + (sPart[2][tid] + sPart[3][tid]);
        (colMode ? g_aggJ : g_aggI)[fixed * CC + tid] = r;
    }
}

// ============================================================
// K3: node model  x_out = [x, aggI, aggJ] @ nw + nb  (K=304)
// 1024 threads: tid>>8 = K-quarter (76 each); tid&255 = f (<240),
// 4 rows per thread; smem reduction over quarters.
// ============================================================
__global__ void __launch_bounds__(1024) node_kernel(
    const float* __restrict__ xin, const float* __restrict__ nw,
    const float* __restrict__ nb, int layer)
{
    const float* x = (layer == 1) ? xin : g_x1;
    float* xout = (layer == 1) ? g_x1 : g_x2;
    __shared__ __align__(16) float s[4][NK];
    __shared__ float part[4][4][FF];
    int row0 = blockIdx.x * 4;
    int tid = threadIdx.x;
    for (int idx = tid; idx < 4 * NK; idx += 1024) {
        int r = idx / NK, k = idx % NK;
        float v;
        if (k < FF)            v = x[(row0 + r) * FF + k];
        else if (k < FF + CC)  v = g_aggI[(row0 + r) * CC + (k - FF)];
        else                   v = g_aggJ[(row0 + r) * CC + (k - FF - CC)];
        s[r][k] = v;
    }
    __syncthreads();

    int kq = tid >> 8;
    int f = tid & 255;
    if (f < FF) {
        const float* wp = nw + f;
        float a0 = 0.f, a1 = 0.f, a2 = 0.f, a3 = 0.f;
#pragma unroll
        for (int k4 = 0; k4 < 19; k4++) {
            int k = kq * 76 + k4 * 4;
            float w0 = __ldg(wp + (k + 0) * FF);
            float w1 = __ldg(wp + (k + 1) * FF);
            float w2 = __ldg(wp + (k + 2) * FF);
            float w3 = __ldg(wp + (k + 3) * FF);
            float4 x0 = *(const float4*)&s[0][k];
            float4 x1 = *(const float4*)&s[1][k];
            float4 x2 = *(const float4*)&s[2][k];
            float4 x3 = *(const float4*)&s[3][k];
            a0 += x0.x * w0 + x0.y * w1 + x0.z * w2 + x0.w * w3;
            a1 += x1.x * w0 + x1.y * w1 + x1.z * w2 + x1.w * w3;
            a2 += x2.x * w0 + x2.y * w1 + x2.z * w2 + x2.w * w3;
            a3 += x3.x * w0 + x3.y * w1 + x3.z * w2 + x3.w * w3;
        }
        part[kq][0][f] = a0;
        part[kq][1][f] = a1;
        part[kq][2][f] = a2;
        part[kq][3][f] = a3;
    }
    __syncthreads();
    if (tid < 4 * FF) {
        int r = tid / FF, f2 = tid % FF;
        float v = (part[0][r][f2] + part[1][r][f2]) +
                  (part[2][r][f2] + part[3][r][f2]) + nb[f2];
        xout[(row0 + r) * FF + f2] = v;
    }
}

// ============================================================
// K4: out = x2 @ dw + db   (400 x 1440, K=240)
// 512 threads: tid>>8 = K-half (120 each); 16 rows x 256 cols/block
// ============================================================
#define ROWS_O 16
__global__ void __launch_bounds__(512) out_kernel(
    const float* __restrict__ dw, const float* __restrict__ db,
    float* __restrict__ out)
{
    __shared__ __align__(16) float s[ROWS_O][FF];
    __shared__ float part[ROWS_O][256];
    int tid = threadIdx.x;
    int row0 = blockIdx.y * ROWS_O;
    int kh = tid >> 8;
    int tc = tid & 255;
    int col = blockIdx.x * 256 + tc;
    for (int idx = tid; idx < ROWS_O * FF; idx += 512)
        s[idx / FF][idx % FF] = g_x2[row0 * FF + idx];
    __syncthreads();

    bool active = (col < LL);
    float acc[ROWS_O];
#pragma unroll
    for (int r = 0; r < ROWS_O; r++) acc[r] = 0.f;

    if (active) {
        const float* wp = dw + col;
#pragma unroll 5
        for (int k4 = 0; k4 < 30; k4++) {
            int k = kh * 120 + k4 * 4;
            float w0 = __ldg(wp + (k + 0) * LL);
            float w1 = __ldg(wp + (k + 1) * LL);
            float w2 = __ldg(wp + (k + 2) * LL);
            float w3 = __ldg(wp + (k + 3) * LL);
#pragma unroll
            for (int r = 0; r < ROWS_O; r++) {
                float4 xv = *(const float4*)&s[r][k];
                acc[r] += xv.x * w0 + xv.y * w1 + xv.z * w2 + xv.w * w3;
            }
        }
    }
    if (kh == 1 && active) {
#pragma unroll
        for (int r = 0; r < ROWS_O; r++) part[r][tc] = acc[r];
    }
    __syncthreads();
    if (kh == 0 && active) {
        float b = db[col];
#pragma unroll
        for (int r = 0; r < ROWS_O; r++)
            out[(row0 + r) * LL + col] = acc[r] + part[r][tc] + b;
    }
}

// ============================================================
extern "C" void kernel_launch(void* const* d_in, const int* in_sizes, int n_in,
                              void* d_out, int out_size)
{
    const float* x      = (const float*)d_in[0];
    const float* a      = (const float*)d_in[1];
    const float* e      = (const float*)d_in[2];
    const float* c1_sw  = (const float*)d_in[3];
    const float* c1_sb  = (const float*)d_in[4];
    const float* c1_aiw = (const float*)d_in[5];
    const float* c1_aib = (const float*)d_in[6];
    const float* c1_ajw = (const float*)d_in[7];
    const float* c1_ajb = (const float*)d_in[8];
    const float* c1_nw  = (const float*)d_in[9];
    const float* c1_nb  = (const float*)d_in[10];
    const float* c1_ew  = (const float*)d_in[11];
    const float* c1_eb  = (const float*)d_in[12];
    const float* c2_sw  = (const float*)d_in[13];
    const float* c2_sb  = (const float*)d_in[14];
    const float* c2_aiw = (const float*)d_in[15];
    const float* c2_aib = (const float*)d_in[16];
    const float* c2_ajw = (const float*)d_in[17];
    const float* c2_ajb = (const float*)d_in[18];
    const float* c2_nw  = (const float*)d_in[19];
    const float* c2_nb  = (const float*)d_in[20];
    const float* c2_ew  = (const float*)d_in[21];
    const float* c2_eb  = (const float*)d_in[22];
    const float* dw     = (const float*)d_in[23];
    const float* db     = (const float*)d_in[24];
    float* out = (float*)d_out;

    // ---- prep: transpose a, e ----
    prep_kernel<<<dim3(169, 2), 256>>>(a, e);

    // ---- layer 1 ----
    xw_kernel<<<NN / 4, 1024>>>(x, c1_sw, c1_sb, 0);
    pair_kernel<<<2 * NN, 128>>>(e, a, c1_sw, c1_aiw, c1_aib, c1_ajw, c1_ajb,
                                 c1_ew, c1_eb, 1);
    node_kernel<<<NN / 4, 1024>>>(x, c1_nw, c1_nb, 1);

    // ---- layer 2 ----
    xw_kernel<<<NN / 4, 1024>>>(nullptr, c2_sw, c2_sb, 1);
    pair_kernel<<<2 * NN, 128>>>(nullptr, a, c2_sw, c2_aiw, c2_aib, c2_ajw, c2_ajb,
                                 c2_ew, c2_eb, 2);
    node_kernel<<<NN / 4, 1024>>>(nullptr, c2_nw, c2_nb, 2);

    // ---- readout ----
    out_kernel<<<dim3(6, NN / ROWS_O), 512>>>(dw, db, out);
}